// round 10
// baseline (speedup 1.0000x reference)
#include <cuda_runtime.h>
#include <cstdint>

#define N_NODES 50000
#define N_EDGES 800000
#define DIM 128
#define HEADS 8

// ---------------- node-GEMM config (unchanged from R6) ----------------
#define NTILE_M 64
#define NTHREADS 512
#define KTW 517
#define KTA 265
#define SMEM_W_U2 (16 * KTW)
#define SMEM_A_U2 (16 * KTA)
#define NODE_SMEM ((SMEM_W_U2 + SMEM_A_U2) * 8)   // 100096 B
#define NODE_GRID 296

// ---------------- edge kernel config (128-edge tile, 32x32 warp tiles) ----
#define ETILE_M 128
#define ETHREADS 512
#define EKTA 529                      // uint2 stride per k-tile (128 rows*4 + 17 pad)
#define ECS_STRIDE 132                // floats; 528B rows, 16B aligned
#define ESMEM_A_U2 (16 * EKTA)        // 8464 uint2 = 67712 B (Cs 128*132*4=67584 aliases)
#define EDGE_SMEM ((SMEM_W_U2 + ESMEM_A_U2) * 8)  // 133888 B -> 1 CTA/SM
#define EGRID 148

// Scratch (allocation-free rule: __device__ globals)
__device__ float g_Q[N_NODES * DIM];
__device__ float g_K[N_NODES * DIM];
__device__ float g_V[N_NODES * DIM];
__device__ float g_z[N_NODES * HEADS];

// ---------------------------------------------------------------------------
// helpers
// ---------------------------------------------------------------------------
__device__ __forceinline__ uint32_t f2tf32(float f) {
    uint32_t r;
    asm("cvt.rna.tf32.f32 %0, %1;" : "=r"(r) : "f"(f));
    return r;
}

__device__ __forceinline__ void mma8(float c[4], uint32_t a0, uint32_t a1,
                                     uint32_t a2, uint32_t a3,
                                     uint32_t b0, uint32_t b1) {
    asm("mma.sync.aligned.m16n8k8.row.col.f32.tf32.tf32.f32 "
        "{%0,%1,%2,%3}, {%4,%5,%6,%7}, {%8,%9}, {%0,%1,%2,%3};\n"
        : "+f"(c[0]), "+f"(c[1]), "+f"(c[2]), "+f"(c[3])
        : "r"(a0), "r"(a1), "r"(a2), "r"(a3), "r"(b0), "r"(b1));
}

__device__ __forceinline__ void red_add_v4(float* p, float4 v) {
    asm volatile("red.global.add.v4.f32 [%0], {%1,%2,%3,%4};"
                 :: "l"(p), "f"(v.x), "f"(v.y), "f"(v.z), "f"(v.w) : "memory");
}

__device__ __forceinline__ void red_add_f32(float* p, float v) {
    asm volatile("red.global.add.f32 [%0], %1;" :: "l"(p), "f"(v) : "memory");
}

// Stage W[128][128] (row-major, k x n) into packed tf32 layout:
// within k-tile, uint32 index = n*8 + p*2 + slot, p=k&3, slot=(k>>2)&1
__device__ __forceinline__ void stage_W(uint2* Wp, const float* __restrict__ W,
                                        int nthreads) {
    int tid = threadIdx.x;
#pragma unroll 1
    for (int idx = tid; idx < 4096; idx += nthreads) {
        int k = idx & 127;
        int c = idx >> 7;             // float4 index over n
        float4 v = *(const float4*)&W[k * DIM + c * 4];
        int kt = k >> 3, p = k & 3, slot = (k >> 2) & 1;
        uint32_t* w32 = (uint32_t*)(Wp + kt * KTW);
        int n0 = c * 4;
        w32[(n0 + 0) * 8 + p * 2 + slot] = f2tf32(v.x);
        w32[(n0 + 1) * 8 + p * 2 + slot] = f2tf32(v.y);
        w32[(n0 + 2) * 8 + p * 2 + slot] = f2tf32(v.z);
        w32[(n0 + 3) * 8 + p * 2 + slot] = f2tf32(v.w);
    }
}

// ---------------------------------------------------------------------------
// edge kernel: 128-edge tiles, 16 warps of 32x32, pipelined prefetch
// thread (r, j): r = row in tile (0..127), j = k-tile (0..15);
// loads A[r][j*8 .. j*8+7] as two float4, stores 4 STS.64 pairs.
// ---------------------------------------------------------------------------
__device__ __forceinline__ void prefetch_E(float4 v1[4], float4 v2[4],
                                           const float* __restrict__ E,
                                           int row0, int tid) {
#pragma unroll
    for (int it = 0; it < 4; ++it) {
        int idx = it * ETHREADS + tid;    // 0..2047
        int r = idx >> 4;                 // 0..127
        int j = idx & 15;                 // k-tile
        const float4* p = (const float4*)&E[(size_t)(row0 + r) * DIM + j * 8];
        v1[it] = __ldcs(&p[0]);
        v2[it] = __ldcs(&p[1]);
    }
}

__device__ __forceinline__ void store_E(uint2* Ap, const float4 v1[4],
                                        const float4 v2[4], int tid) {
#pragma unroll
    for (int it = 0; it < 4; ++it) {
        int idx = it * ETHREADS + tid;
        int r = idx >> 4;
        int j = idx & 15;
        uint2* base = Ap + j * EKTA + r * 4;
        base[0] = make_uint2(f2tf32(v1[it].x), f2tf32(v2[it].x));
        base[1] = make_uint2(f2tf32(v1[it].y), f2tf32(v2[it].y));
        base[2] = make_uint2(f2tf32(v1[it].z), f2tf32(v2[it].z));
        base[3] = make_uint2(f2tf32(v1[it].w), f2tf32(v2[it].w));
    }
}

// Warp mainloop: 32 rows x 32 cols per warp, K=128
__device__ __forceinline__ void mma_tile32(const uint2* Ap, const uint2* Wp,
                                           int wm, int wn, int lane,
                                           float c[2][4][4]) {
#pragma unroll 4
    for (int kt = 0; kt < 16; ++kt) {
        const uint2* ak = Ap + kt * EKTA;
        const uint2* wk = Wp + kt * KTW;
        uint2 a00 = ak[wm * 4 + lane];
        uint2 a01 = ak[(wm + 8) * 4 + lane];
        uint2 a10 = ak[(wm + 16) * 4 + lane];
        uint2 a11 = ak[(wm + 24) * 4 + lane];
#pragma unroll
        for (int nf = 0; nf < 4; ++nf) {
            uint2 b = wk[(wn + nf * 8) * 4 + lane];
            mma8(c[0][nf], a00.x, a01.x, a00.y, a01.y, b.x, b.y);
            mma8(c[1][nf], a10.x, a11.x, a10.y, a11.y, b.x, b.y);
        }
    }
}

__global__ __launch_bounds__(ETHREADS, 1)
void gemm_edge(const float* __restrict__ Ein, const float* __restrict__ W,
               const float* __restrict__ bias, const int* __restrict__ src,
               const int* __restrict__ dst, float* __restrict__ hacc,
               float* __restrict__ eout) {
    extern __shared__ uint2 smem[];
    uint2* Wp = smem;
    uint2* Ap = smem + SMEM_W_U2;
    float* Cs = (float*)Ap;   // union: C staging reuses A region
    int tid = threadIdx.x, lane = tid & 31, warp = tid >> 5;
    int wm = (warp & 3) * 32, wn = (warp >> 2) * 32;
    int g = lane >> 2, t = lane & 3;

    stage_W(Wp, W, ETHREADS);
    float4 be4 = *(const float4*)&bias[lane * 4];

    const int nTiles = N_EDGES / ETILE_M;   // 6250 exact
    int tile = blockIdx.x;
    float4 cur1[4], cur2[4];
    if (tile < nTiles) prefetch_E(cur1, cur2, Ein, tile * ETILE_M, tid);
    __syncthreads();

#pragma unroll 1
    for (; tile < nTiles; tile += gridDim.x) {
        store_E(Ap, cur1, cur2, tid);
        __syncthreads();
        float c[2][4][4];
#pragma unroll
        for (int i = 0; i < 2; ++i)
#pragma unroll
            for (int j = 0; j < 4; ++j)
#pragma unroll
                for (int k = 0; k < 4; ++k) c[i][j][k] = 0.f;
        mma_tile32(Ap, Wp, wm, wn, lane, c);
        // prefetch next tile: LDGs fly during Cs write + gather/scatter epilogue
        int nxt = tile + gridDim.x;
        if (nxt < nTiles) prefetch_E(cur1, cur2, Ein, nxt * ETILE_M, tid);
        __syncthreads();  // all Ap reads done -> safe to alias with Cs
#pragma unroll
        for (int mf = 0; mf < 2; ++mf) {
            int rr = wm + mf * 16 + g;
#pragma unroll
            for (int nf = 0; nf < 4; ++nf) {
                int col = wn + nf * 8 + t * 2;
                *(float2*)&Cs[rr * ECS_STRIDE + col] =
                    make_float2(c[mf][nf][0], c[mf][nf][1]);
                *(float2*)&Cs[(rr + 8) * ECS_STRIDE + col] =
                    make_float2(c[mf][nf][2], c[mf][nf][3]);
            }
        }
        __syncthreads();

        // epilogue: each warp owns 8 edges of this tile
        int rbase = warp * 8;
        int ebase = tile * ETILE_M + rbase;
        int sn[8], dn[8];
#pragma unroll
        for (int i = 0; i < 8; ++i) {
            sn[i] = __ldg(&src[ebase + i]);
            dn[i] = __ldg(&dst[ebase + i]);
        }
#pragma unroll 2
        for (int i = 0; i < 8; ++i) {
            float4 q = *(const float4*)&g_Q[(size_t)dn[i] * DIM + lane * 4];
            float4 kk = *(const float4*)&g_K[(size_t)sn[i] * DIM + lane * 4];
            float4 vv = *(const float4*)&g_V[(size_t)sn[i] * DIM + lane * 4];
            float4 pr = *(float4*)&Cs[(rbase + i) * ECS_STRIDE + lane * 4];
            pr.x += be4.x; pr.y += be4.y; pr.z += be4.z; pr.w += be4.w;
            float4 sc;
            sc.x = q.x * kk.x * 0.25f * pr.x;
            sc.y = q.y * kk.y * 0.25f * pr.y;
            sc.z = q.z * kk.z * 0.25f * pr.z;
            sc.w = q.w * kk.w * 0.25f * pr.w;
            __stcs((float4*)&eout[(size_t)(ebase + i) * DIM + lane * 4], sc);
            float hs = sc.x + sc.y + sc.z + sc.w;
            hs += __shfl_xor_sync(0xffffffffu, hs, 1);
            hs += __shfl_xor_sync(0xffffffffu, hs, 2);
            float s = expf(fminf(fmaxf(hs, -5.f), 5.f));
            float4 add = make_float4(vv.x * s, vv.y * s, vv.z * s, vv.w * s);
            red_add_v4(&hacc[(size_t)dn[i] * DIM + lane * 4], add);
            if ((lane & 3) == 0)
                red_add_f32(&g_z[dn[i] * HEADS + (lane >> 2)], s);
        }
        __syncthreads();  // Cs consumed before next tile's store_E
    }
}

// ---------------------------------------------------------------------------
// node-GEMM path (mma.sync fragments) — unchanged from R6 (passing)
// ---------------------------------------------------------------------------
__device__ __forceinline__ void prefetch_node(float4 v[4], const float* __restrict__ A,
                                              int row0, int M, int tid) {
#pragma unroll
    for (int it = 0; it < 4; ++it) {
        int idx = it * NTHREADS + tid;
        int r = idx >> 5, c = idx & 31;
        int grow = row0 + r;
        v[it] = (grow < M) ? __ldg((const float4*)&A[(size_t)grow * DIM + c * 4])
                           : make_float4(0.f, 0.f, 0.f, 0.f);
    }
}

__device__ __forceinline__ void store_node(uint2* Ap, const float4 v[4], int tid) {
#pragma unroll
    for (int it = 0; it < 4; ++it) {
        int idx = it * NTHREADS + tid;
        int r = idx >> 5, c = idx & 31;
        int kt = c >> 1, slot = c & 1;
        uint32_t* b32 = (uint32_t*)(Ap + kt * KTA + r * 4);
        b32[0 * 2 + slot] = f2tf32(v[it].x);
        b32[1 * 2 + slot] = f2tf32(v[it].y);
        b32[2 * 2 + slot] = f2tf32(v[it].z);
        b32[3 * 2 + slot] = f2tf32(v[it].w);
    }
}

__global__ __launch_bounds__(NTHREADS, 2)
void gemm_node(const float* __restrict__ A,
               const float* __restrict__ W0, const float* __restrict__ W1,
               const float* __restrict__ W2, const float* __restrict__ B0,
               const float* __restrict__ B1, const float* __restrict__ B2,
               float* __restrict__ O0, float* __restrict__ O1,
               float* __restrict__ O2, int M) {
    extern __shared__ uint2 smem2[];
    uint2* Wp = smem2;
    uint2* Ap = smem2 + SMEM_W_U2;
    int which = blockIdx.y;
    const float* W = (which == 0) ? W0 : (which == 1) ? W1 : W2;
    const float* bias = (which == 0) ? B0 : (which == 1) ? B1 : B2;
    float* out = (which == 0) ? O0 : (which == 1) ? O1 : O2;

    int tid = threadIdx.x, lane = tid & 31, warp = tid >> 5;
    int wm = (warp & 3) * 16, wn = (warp >> 2) * 32;
    int g = lane >> 2, t = lane & 3;

    stage_W(Wp, W, NTHREADS);
    float2 bias2[4];
#pragma unroll
    for (int nf = 0; nf < 4; ++nf)
        bias2[nf] = *(const float2*)&bias[wn + nf * 8 + t * 2];

    int nTiles = (M + NTILE_M - 1) / NTILE_M;
    int tile = blockIdx.x;
    float4 cur[4];
    if (tile < nTiles) prefetch_node(cur, A, tile * NTILE_M, M, tid);
    __syncthreads();

#pragma unroll 1
    for (; tile < nTiles; tile += gridDim.x) {
        store_node(Ap, cur, tid);
        __syncthreads();
        int nxt = tile + gridDim.x;
        if (nxt < nTiles) prefetch_node(cur, A, nxt * NTILE_M, M, tid);
        float c[4][4];
#pragma unroll
        for (int j = 0; j < 4; ++j)
#pragma unroll
            for (int k = 0; k < 4; ++k) c[j][k] = 0.f;
#pragma unroll 4
        for (int kt = 0; kt < 16; ++kt) {
            const uint2* ak = Ap + kt * KTA;
            const uint2* wk = Wp + kt * KTW;
            uint2 a0 = ak[wm * 4 + lane];
            uint2 a1 = ak[(wm + 8) * 4 + lane];
#pragma unroll
            for (int nf = 0; nf < 4; ++nf) {
                uint2 b = wk[(wn + nf * 8) * 4 + lane];
                mma8(c[nf], a0.x, a1.x, a0.y, a1.y, b.x, b.y);
            }
        }
        __syncthreads();
        int r0 = tile * NTILE_M + wm + g;
#pragma unroll
        for (int nf = 0; nf < 4; ++nf) {
            int col = wn + nf * 8 + t * 2;
            if (r0 < M)
                *(float2*)&out[(size_t)r0 * DIM + col] =
                    make_float2(c[nf][0] + bias2[nf].x, c[nf][1] + bias2[nf].y);
            if (r0 + 8 < M)
                *(float2*)&out[(size_t)(r0 + 8) * DIM + col] =
                    make_float2(c[nf][2] + bias2[nf].x, c[nf][3] + bias2[nf].y);
        }
    }
}

// ---------------------------------------------------------------------------
// finalize: h_out = wV / (z + 1e-6)
// ---------------------------------------------------------------------------
__global__ void finalize_kernel(float* __restrict__ hacc) {
    int i = blockIdx.x * blockDim.x + threadIdx.x;
    if (i < N_NODES * DIM) {
        int node = i >> 7;
        int head = (i >> 4) & 7;
        hacc[i] = hacc[i] / (g_z[node * HEADS + head] + 1e-6f);
    }
}

// ---------------------------------------------------------------------------
// launch
// ---------------------------------------------------------------------------
extern "C" void kernel_launch(void* const* d_in, const int* in_sizes, int n_in,
                              void* d_out, int out_size) {
    const float* h  = (const float*)d_in[0];
    const float* e  = (const float*)d_in[1];
    const int*   src = (const int*)d_in[2];
    const int*   dst = (const int*)d_in[3];
    const float* Wq = (const float*)d_in[4];
    const float* bq = (const float*)d_in[5];
    const float* Wk = (const float*)d_in[6];
    const float* bk = (const float*)d_in[7];
    const float* Wv = (const float*)d_in[8];
    const float* bv = (const float*)d_in[9];
    const float* We = (const float*)d_in[10];
    const float* be = (const float*)d_in[11];

    float* out  = (float*)d_out;
    float* hacc = out;                               // [N,H,D] accumulator -> h_out
    float* eout = out + (size_t)N_NODES * DIM;       // [E,H,D] e_out

    float *qp, *kp, *vp, *zp;
    cudaGetSymbolAddress((void**)&qp, g_Q);
    cudaGetSymbolAddress((void**)&kp, g_K);
    cudaGetSymbolAddress((void**)&vp, g_V);
    cudaGetSymbolAddress((void**)&zp, g_z);

    cudaFuncSetAttribute(gemm_node, cudaFuncAttributeMaxDynamicSharedMemorySize, NODE_SMEM);
    cudaFuncSetAttribute(gemm_edge, cudaFuncAttributeMaxDynamicSharedMemorySize, EDGE_SMEM);

    cudaMemsetAsync(hacc, 0, (size_t)N_NODES * DIM * sizeof(float));
    cudaMemsetAsync(zp, 0, (size_t)N_NODES * HEADS * sizeof(float));

    dim3 ngrid(NODE_GRID, 3);
    gemm_node<<<ngrid, NTHREADS, NODE_SMEM>>>(h, Wq, Wk, Wv, bq, bk, bv,
                                              qp, kp, vp, N_NODES);
    gemm_edge<<<EGRID, ETHREADS, EDGE_SMEM>>>(e, We, be, src, dst, hacc, eout);
    finalize_kernel<<<(N_NODES * DIM + 255) / 256, 256>>>(hacc);
}

// round 11
// speedup vs baseline: 1.1244x; 1.1244x over previous
#include <cuda_runtime.h>
#include <cstdint>

#define N_NODES 50000
#define N_EDGES 800000
#define DIM 128
#define HEADS 8
#define TILE_M 64
#define THREADS 512
#define KTW 517                       // uint2 stride per k-tile for W (128 cols * 4 + 5 pad)
#define KTA 265                       // uint2 stride per k-tile for A (64 rows * 4 + 9 pad)
#define CS_STRIDE 132                 // float stride for epilogue C staging (528B, 16B-aligned rows)
#define SMEM_W_U2 (16 * KTW)          // 8272 uint2 = 66176 B
#define SMEM_A_U2 (16 * KTA)          // 4240 uint2 = 33920 B (Cs: 64*132*4=33792 B aliases, fits)
#define SMEM_BYTES ((SMEM_W_U2 + SMEM_A_U2) * 8)  // 100096 B -> 2 CTAs/SM
#define GRID 296                      // 2 per SM * 148

// Scratch (allocation-free rule: __device__ globals)
__device__ float g_Q[N_NODES * DIM];
__device__ float g_K[N_NODES * DIM];
__device__ float g_V[N_NODES * DIM];
__device__ float g_z[N_NODES * HEADS];

// ---------------------------------------------------------------------------
// helpers
// ---------------------------------------------------------------------------
__device__ __forceinline__ uint32_t f2tf32(float f) {
    uint32_t r;
    asm("cvt.rna.tf32.f32 %0, %1;" : "=r"(r) : "f"(f));
    return r;
}

__device__ __forceinline__ void mma8(float c[4], uint32_t a0, uint32_t a1,
                                     uint32_t a2, uint32_t a3,
                                     uint32_t b0, uint32_t b1) {
    asm("mma.sync.aligned.m16n8k8.row.col.f32.tf32.tf32.f32 "
        "{%0,%1,%2,%3}, {%4,%5,%6,%7}, {%8,%9}, {%0,%1,%2,%3};\n"
        : "+f"(c[0]), "+f"(c[1]), "+f"(c[2]), "+f"(c[3])
        : "r"(a0), "r"(a1), "r"(a2), "r"(a3), "r"(b0), "r"(b1));
}

// NOTE: no "memory" clobber — these are fire-and-forget reductions to buffers
// never read inside this kernel; the clobber was serializing the epilogue by
// blocking load hoisting across iterations.
__device__ __forceinline__ void red_add_v4(float* p, float4 v) {
    asm volatile("red.global.add.v4.f32 [%0], {%1,%2,%3,%4};"
                 :: "l"(p), "f"(v.x), "f"(v.y), "f"(v.z), "f"(v.w));
}

__device__ __forceinline__ void red_add_f32(float* p, float v) {
    asm volatile("red.global.add.f32 [%0], %1;" :: "l"(p), "f"(v));
}

// Stage W[128][128] (row-major, k x n) into packed tf32 layout:
// within k-tile, uint32 index = n*8 + p*2 + slot, p=k&3, slot=(k>>2)&1
__device__ __forceinline__ void stage_W(uint2* Wp, const float* __restrict__ W) {
    int tid = threadIdx.x;
#pragma unroll 1
    for (int it = 0; it < 8; ++it) {
        int idx = it * THREADS + tid; // 0..4095
        int k = idx & 127;
        int c = idx >> 7;             // float4 index over n
        float4 v = *(const float4*)&W[k * DIM + c * 4];
        int kt = k >> 3, p = k & 3, slot = (k >> 2) & 1;
        uint32_t* w32 = (uint32_t*)(Wp + kt * KTW);
        int n0 = c * 4;
        w32[(n0 + 0) * 8 + p * 2 + slot] = f2tf32(v.x);
        w32[(n0 + 1) * 8 + p * 2 + slot] = f2tf32(v.y);
        w32[(n0 + 2) * 8 + p * 2 + slot] = f2tf32(v.z);
        w32[(n0 + 3) * 8 + p * 2 + slot] = f2tf32(v.w);
    }
}

// Prefetch A tile into registers (4 float4 per thread). stream=evict-first.
template <bool STREAM>
__device__ __forceinline__ void prefetch_A(float4 v[4], const float* __restrict__ A,
                                           int row0, int M, int tid) {
#pragma unroll
    for (int it = 0; it < 4; ++it) {
        int idx = it * THREADS + tid; // 0..2047
        int r = idx >> 5;             // row in tile (0..63)
        int c = idx & 31;             // float4 index over k
        int grow = row0 + r;
        if (grow < M) {
            const float4* p = (const float4*)&A[(size_t)grow * DIM + c * 4];
            v[it] = STREAM ? __ldcs(p) : __ldg(p);
        } else {
            v[it] = make_float4(0.f, 0.f, 0.f, 0.f);
        }
    }
}

// Store prefetched regs into packed tf32 A layout.
__device__ __forceinline__ void store_A(uint2* Ap, const float4 v[4], int tid) {
#pragma unroll
    for (int it = 0; it < 4; ++it) {
        int idx = it * THREADS + tid;
        int r = idx >> 5;
        int c = idx & 31;
        int kt = c >> 1, slot = c & 1;
        uint32_t* b32 = (uint32_t*)(Ap + kt * KTA + r * 4);
        b32[0 * 2 + slot] = f2tf32(v[it].x);
        b32[1 * 2 + slot] = f2tf32(v[it].y);
        b32[2 * 2 + slot] = f2tf32(v[it].z);
        b32[3 * 2 + slot] = f2tf32(v[it].w);
    }
}

// Warp mainloop: 16 rows x 32 cols per warp, K=128
__device__ __forceinline__ void mma_tile(const uint2* Ap, const uint2* Wp,
                                         int wm, int wn, int lane,
                                         float c[4][4]) {
#pragma unroll 4
    for (int kt = 0; kt < 16; ++kt) {
        const uint2* ak = Ap + kt * KTA;
        const uint2* wk = Wp + kt * KTW;
        uint2 a0 = ak[wm * 4 + lane];             // rows wm+g      -> (a0, a2)
        uint2 a1 = ak[(wm + 8) * 4 + lane];       // rows wm+8+g    -> (a1, a3)
#pragma unroll
        for (int nf = 0; nf < 4; ++nf) {
            uint2 b = wk[(wn + nf * 8) * 4 + lane];
            mma8(c[nf], a0.x, a1.x, a0.y, a1.y, b.x, b.y);
        }
    }
}

// ---------------------------------------------------------------------------
// Fused node projections: out_w[M,128] = h @ W_w + b_w for w = blockIdx.y
// ---------------------------------------------------------------------------
__global__ __launch_bounds__(THREADS, 2)
void gemm_node(const float* __restrict__ A,
               const float* __restrict__ W0, const float* __restrict__ W1,
               const float* __restrict__ W2, const float* __restrict__ B0,
               const float* __restrict__ B1, const float* __restrict__ B2,
               float* __restrict__ O0, float* __restrict__ O1,
               float* __restrict__ O2, int M) {
    extern __shared__ uint2 smem[];
    uint2* Wp = smem;
    uint2* Ap = smem + SMEM_W_U2;
    int which = blockIdx.y;
    const float* W = (which == 0) ? W0 : (which == 1) ? W1 : W2;
    const float* bias = (which == 0) ? B0 : (which == 1) ? B1 : B2;
    float* out = (which == 0) ? O0 : (which == 1) ? O1 : O2;

    int tid = threadIdx.x, lane = tid & 31, warp = tid >> 5;
    int wm = (warp & 3) * 16, wn = (warp >> 2) * 32;
    int g = lane >> 2, t = lane & 3;

    stage_W(Wp, W);
    float2 bias2[4];
#pragma unroll
    for (int nf = 0; nf < 4; ++nf)
        bias2[nf] = *(const float2*)&bias[wn + nf * 8 + t * 2];

    int nTiles = (M + TILE_M - 1) / TILE_M;
    int tile = blockIdx.x;
    float4 cur[4];
    if (tile < nTiles) prefetch_A<false>(cur, A, tile * TILE_M, M, tid);
    __syncthreads();

#pragma unroll 1
    for (; tile < nTiles; tile += gridDim.x) {
        store_A(Ap, cur, tid);
        __syncthreads();
        int nxt = tile + gridDim.x;
        if (nxt < nTiles) prefetch_A<false>(cur, A, nxt * TILE_M, M, tid);
        float c[4][4];
#pragma unroll
        for (int j = 0; j < 4; ++j)
#pragma unroll
            for (int k = 0; k < 4; ++k) c[j][k] = 0.f;
        mma_tile(Ap, Wp, wm, wn, lane, c);
        __syncthreads();
        int r0 = tile * TILE_M + wm + g;
#pragma unroll
        for (int nf = 0; nf < 4; ++nf) {
            int col = wn + nf * 8 + t * 2;
            if (r0 < M)
                *(float2*)&out[(size_t)r0 * DIM + col] =
                    make_float2(c[nf][0] + bias2[nf].x,
                                c[nf][1] + bias2[nf].y);
            if (r0 + 8 < M)
                *(float2*)&out[(size_t)(r0 + 8) * DIM + col] =
                    make_float2(c[nf][2] + bias2[nf].x,
                                c[nf][3] + bias2[nf].y);
        }
    }
}

// ---------------------------------------------------------------------------
// Fused edge kernel: proj = e @ We + be, then score/e_out/s/scatter
// ---------------------------------------------------------------------------
__global__ __launch_bounds__(THREADS, 2)
void gemm_edge(const float* __restrict__ Ein, const float* __restrict__ W,
               const float* __restrict__ bias, const int* __restrict__ src,
               const int* __restrict__ dst, float* __restrict__ hacc,
               float* __restrict__ eout) {
    extern __shared__ uint2 smem[];
    uint2* Wp = smem;
    uint2* Ap = smem + SMEM_W_U2;
    float* Cs = (float*)Ap;  // union: C staging reuses A region
    int tid = threadIdx.x, lane = tid & 31, warp = tid >> 5;
    int wm = (warp & 3) * 16, wn = (warp >> 2) * 32;
    int g = lane >> 2, t = lane & 3;

    stage_W(Wp, W);
    float4 be4 = *(const float4*)&bias[lane * 4];

    const int nTiles = N_EDGES / TILE_M;  // 12500 exact
    int tile = blockIdx.x;
    float4 cur[4];
    if (tile < nTiles) prefetch_A<true>(cur, Ein, tile * TILE_M, N_EDGES, tid);
    __syncthreads();

#pragma unroll 1
    for (; tile < nTiles; tile += gridDim.x) {
        store_A(Ap, cur, tid);
        __syncthreads();
        float c[4][4];
#pragma unroll
        for (int j = 0; j < 4; ++j)
#pragma unroll
            for (int k = 0; k < 4; ++k) c[j][k] = 0.f;
        mma_tile(Ap, Wp, wm, wn, lane, c);
        // prefetch next tile: overlaps Cs-write + gather/scatter epilogue
        int nxt = tile + gridDim.x;
        if (nxt < nTiles) prefetch_A<true>(cur, Ein, nxt * TILE_M, N_EDGES, tid);
        __syncthreads();  // Ap reads done -> safe to overwrite with Cs
        {
            int rr = wm + g;
#pragma unroll
            for (int nf = 0; nf < 4; ++nf) {
                int col = wn + nf * 8 + t * 2;
                *(float2*)&Cs[rr * CS_STRIDE + col] =
                    make_float2(c[nf][0], c[nf][1]);
                *(float2*)&Cs[(rr + 8) * CS_STRIDE + col] =
                    make_float2(c[nf][2], c[nf][3]);
            }
        }
        __syncthreads();

        // epilogue: each warp owns 4 edges; process 2 at a time with
        // gathers batched ahead of math so L2 latency overlaps.
        int rbase = warp * 4;
        int ebase = tile * TILE_M + rbase;
        int sn[4], dn[4];
#pragma unroll
        for (int i = 0; i < 4; ++i) {
            sn[i] = __ldg(&src[ebase + i]);
            dn[i] = __ldg(&dst[ebase + i]);
        }
#pragma unroll
        for (int i = 0; i < 4; i += 2) {
            // batch all global/shared loads for both edges first
            float4 q0 = *(const float4*)&g_Q[(size_t)dn[i] * DIM + lane * 4];
            float4 k0 = *(const float4*)&g_K[(size_t)sn[i] * DIM + lane * 4];
            float4 v0 = *(const float4*)&g_V[(size_t)sn[i] * DIM + lane * 4];
            float4 q1 = *(const float4*)&g_Q[(size_t)dn[i + 1] * DIM + lane * 4];
            float4 k1 = *(const float4*)&g_K[(size_t)sn[i + 1] * DIM + lane * 4];
            float4 v1 = *(const float4*)&g_V[(size_t)sn[i + 1] * DIM + lane * 4];
            float4 p0 = *(float4*)&Cs[(rbase + i) * CS_STRIDE + lane * 4];
            float4 p1 = *(float4*)&Cs[(rbase + i + 1) * CS_STRIDE + lane * 4];
            p0.x += be4.x; p0.y += be4.y; p0.z += be4.z; p0.w += be4.w;
            p1.x += be4.x; p1.y += be4.y; p1.z += be4.z; p1.w += be4.w;

            float4 s0, s1;
            s0.x = q0.x * k0.x * 0.25f * p0.x;
            s0.y = q0.y * k0.y * 0.25f * p0.y;
            s0.z = q0.z * k0.z * 0.25f * p0.z;
            s0.w = q0.w * k0.w * 0.25f * p0.w;
            s1.x = q1.x * k1.x * 0.25f * p1.x;
            s1.y = q1.y * k1.y * 0.25f * p1.y;
            s1.z = q1.z * k1.z * 0.25f * p1.z;
            s1.w = q1.w * k1.w * 0.25f * p1.w;
            __stcs((float4*)&eout[(size_t)(ebase + i) * DIM + lane * 4], s0);
            __stcs((float4*)&eout[(size_t)(ebase + i + 1) * DIM + lane * 4], s1);

            float h0 = s0.x + s0.y + s0.z + s0.w;
            float h1 = s1.x + s1.y + s1.z + s1.w;
            h0 += __shfl_xor_sync(0xffffffffu, h0, 1);
            h0 += __shfl_xor_sync(0xffffffffu, h0, 2);
            h1 += __shfl_xor_sync(0xffffffffu, h1, 1);
            h1 += __shfl_xor_sync(0xffffffffu, h1, 2);
            float e0 = expf(fminf(fmaxf(h0, -5.f), 5.f));
            float e1 = expf(fminf(fmaxf(h1, -5.f), 5.f));

            red_add_v4(&hacc[(size_t)dn[i] * DIM + lane * 4],
                       make_float4(v0.x * e0, v0.y * e0, v0.z * e0, v0.w * e0));
            red_add_v4(&hacc[(size_t)dn[i + 1] * DIM + lane * 4],
                       make_float4(v1.x * e1, v1.y * e1, v1.z * e1, v1.w * e1));
            if ((lane & 3) == 0) {
                red_add_f32(&g_z[dn[i] * HEADS + (lane >> 2)], e0);
                red_add_f32(&g_z[dn[i + 1] * HEADS + (lane >> 2)], e1);
            }
        }
        __syncthreads();  // Cs reads done before next tile's store_A
    }
}

// ---------------------------------------------------------------------------
// finalize: h_out = wV / (z + 1e-6)
// ---------------------------------------------------------------------------
__global__ void finalize_kernel(float* __restrict__ hacc) {
    int i = blockIdx.x * blockDim.x + threadIdx.x;
    if (i < N_NODES * DIM) {
        int node = i >> 7;
        int head = (i >> 4) & 7;
        hacc[i] = hacc[i] / (g_z[node * HEADS + head] + 1e-6f);
    }
}

// ---------------------------------------------------------------------------
// launch
// ---------------------------------------------------------------------------
extern "C" void kernel_launch(void* const* d_in, const int* in_sizes, int n_in,
                              void* d_out, int out_size) {
    const float* h  = (const float*)d_in[0];
    const float* e  = (const float*)d_in[1];
    const int*   src = (const int*)d_in[2];
    const int*   dst = (const int*)d_in[3];
    const float* Wq = (const float*)d_in[4];
    const float* bq = (const float*)d_in[5];
    const float* Wk = (const float*)d_in[6];
    const float* bk = (const float*)d_in[7];
    const float* Wv = (const float*)d_in[8];
    const float* bv = (const float*)d_in[9];
    const float* We = (const float*)d_in[10];
    const float* be = (const float*)d_in[11];

    float* out  = (float*)d_out;
    float* hacc = out;                               // [N,H,D] accumulator -> h_out
    float* eout = out + (size_t)N_NODES * DIM;       // [E,H,D] e_out

    float *qp, *kp, *vp, *zp;
    cudaGetSymbolAddress((void**)&qp, g_Q);
    cudaGetSymbolAddress((void**)&kp, g_K);
    cudaGetSymbolAddress((void**)&vp, g_V);
    cudaGetSymbolAddress((void**)&zp, g_z);

    cudaFuncSetAttribute(gemm_node, cudaFuncAttributeMaxDynamicSharedMemorySize, SMEM_BYTES);
    cudaFuncSetAttribute(gemm_edge, cudaFuncAttributeMaxDynamicSharedMemorySize, SMEM_BYTES);

    cudaMemsetAsync(hacc, 0, (size_t)N_NODES * DIM * sizeof(float));
    cudaMemsetAsync(zp, 0, (size_t)N_NODES * HEADS * sizeof(float));

    dim3 ngrid(GRID, 3);
    gemm_node<<<ngrid, THREADS, SMEM_BYTES>>>(h, Wq, Wk, Wv, bq, bk, bv,
                                              qp, kp, vp, N_NODES);
    gemm_edge<<<GRID, THREADS, SMEM_BYTES>>>(e, We, be, src, dst, hacc, eout);
    finalize_kernel<<<(N_NODES * DIM + 255) / 256, 256>>>(hacc);
}

// round 12
// speedup vs baseline: 1.4920x; 1.3269x over previous
#include <cuda_runtime.h>
#include <cuda_fp16.h>
#include <cstdint>

#define N_NODES 50000
#define N_EDGES 800000
#define DIM 128
#define HEADS 8
#define TILE_M 64
#define THREADS 512
#define KTW_H 517                 // uint2 per k-tile for W (128 n * 4 + 5 pad)
#define KTA_H 261                 // uint2 per k-tile for A (64 rows * 4 + 5 pad)
#define CS_STRIDE 132             // float stride for Cs rows (528B, 16B aligned)
#define SMEM_W_U2 (8 * KTW_H)     // 4136 uint2 = 33088 B
#define SMEM_A_U2 (8 * KTA_H)     // 2088 uint2 = 16704 B
#define NODE_SMEM ((SMEM_W_U2 + SMEM_A_U2) * 8)                 // 49792 B
#define EDGE_SMEM (NODE_SMEM + TILE_M * CS_STRIDE * 4)          // 83584 B -> 2 CTAs/SM
#define GRID 296

// Scratch (allocation-free rule: __device__ globals)
__device__ float g_Q[N_NODES * DIM];
__device__ float g_K[N_NODES * DIM];
__device__ float g_V[N_NODES * DIM];
__device__ float g_z[N_NODES * HEADS];

// ---------------------------------------------------------------------------
// helpers
// ---------------------------------------------------------------------------
__device__ __forceinline__ uint32_t pack_h2(float lo, float hi) {
    __half2 h = __floats2half2_rn(lo, hi);   // .x -> low 16 bits
    return *reinterpret_cast<uint32_t*>(&h);
}

// m16n8k16 f16 mma, f32 accumulate.
// a0:(g,2t..2t+1) a1:(g+8,2t..) a2:(g,8+2t..) a3:(g+8,8+2t..)
// b0:(k=2t..2t+1,n=g) b1:(k=8+2t..,n=g)
__device__ __forceinline__ void mma16(float c[4], uint32_t a0, uint32_t a1,
                                      uint32_t a2, uint32_t a3,
                                      uint32_t b0, uint32_t b1) {
    asm("mma.sync.aligned.m16n8k16.row.col.f32.f16.f16.f32 "
        "{%0,%1,%2,%3}, {%4,%5,%6,%7}, {%8,%9}, {%0,%1,%2,%3};\n"
        : "+f"(c[0]), "+f"(c[1]), "+f"(c[2]), "+f"(c[3])
        : "r"(a0), "r"(a1), "r"(a2), "r"(a3), "r"(b0), "r"(b1));
}

__device__ __forceinline__ void red_add_v4(float* p, float4 v) {
    asm volatile("red.global.add.v4.f32 [%0], {%1,%2,%3,%4};"
                 :: "l"(p), "f"(v.x), "f"(v.y), "f"(v.z), "f"(v.w));
}

__device__ __forceinline__ void red_add_f32(float* p, float v) {
    asm volatile("red.global.add.f32 [%0], %1;" :: "l"(p), "f"(v));
}

// Stage W[128][128] (row-major k x n) into fp16 fragment layout:
// Wp[kt*KTW_H + n*4 + t] = uint2{ h2(W[kt*16+2t][n], W[kt*16+2t+1][n]),
//                                 h2(W[kt*16+8+2t][n], W[kt*16+9+2t][n]) }
__device__ __forceinline__ void stage_W(uint2* Wp, const float* __restrict__ W) {
    int tid = threadIdx.x;
#pragma unroll 1
    for (int idx = tid; idx < 4096; idx += THREADS) {
        int n = idx & 127;
        int rest = idx >> 7;       // 0..31
        int tp = rest & 3;
        int kt = rest >> 2;        // 0..7
        int k0 = kt * 16 + tp * 2;
        uint32_t lo = pack_h2(W[k0 * DIM + n], W[(k0 + 1) * DIM + n]);
        uint32_t hi = pack_h2(W[(k0 + 8) * DIM + n], W[(k0 + 9) * DIM + n]);
        Wp[kt * KTW_H + n * 4 + tp] = make_uint2(lo, hi);
    }
}

// Prefetch: thread owns (row r = tid>>3, k-tile kt = tid&7): 16 consecutive k.
template <bool STREAM>
__device__ __forceinline__ void prefetch_A(float4 v[4], const float* __restrict__ A,
                                           int row0, int M, int tid) {
    int r = tid >> 3, kt = tid & 7;
    int grow = row0 + r;
    if (grow < M) {
        const float4* p = (const float4*)&A[(size_t)grow * DIM + kt * 16];
#pragma unroll
        for (int i = 0; i < 4; ++i) v[i] = STREAM ? __ldcs(p + i) : __ldg(p + i);
    } else {
#pragma unroll
        for (int i = 0; i < 4; ++i) v[i] = make_float4(0.f, 0.f, 0.f, 0.f);
    }
}

// Store to fragment layout: Ap[kt*KTA_H + r*4 + t] =
//   uint2{ h2(k=2t,2t+1), h2(k=8+2t,9+2t) }  (k local to this k-tile)
__device__ __forceinline__ void store_A(uint2* Ap, const float4 v[4], int tid) {
    int r = tid >> 3, kt = tid & 7;
    uint2* base = Ap + kt * KTA_H + r * 4;
    base[0] = make_uint2(pack_h2(v[0].x, v[0].y), pack_h2(v[2].x, v[2].y));
    base[1] = make_uint2(pack_h2(v[0].z, v[0].w), pack_h2(v[2].z, v[2].w));
    base[2] = make_uint2(pack_h2(v[1].x, v[1].y), pack_h2(v[3].x, v[3].y));
    base[3] = make_uint2(pack_h2(v[1].z, v[1].w), pack_h2(v[3].z, v[3].w));
}

// Warp mainloop: 16 rows x 32 cols per warp, K=128 (8 k-tiles of 16)
__device__ __forceinline__ void mma_tile(const uint2* Ap, const uint2* Wp,
                                         int wm, int wn, int lane,
                                         float c[4][4]) {
#pragma unroll
    for (int kt = 0; kt < 8; ++kt) {
        const uint2* ak = Ap + kt * KTA_H;
        const uint2* wk = Wp + kt * KTW_H;
        uint2 aA = ak[wm * 4 + lane];             // (a0, a2): row wm+g
        uint2 aB = ak[(wm + 8) * 4 + lane];       // (a1, a3): row wm+8+g
#pragma unroll
        for (int nf = 0; nf < 4; ++nf) {
            uint2 b = wk[(wn + nf * 8) * 4 + lane];
            mma16(c[nf], aA.x, aB.x, aA.y, aB.y, b.x, b.y);
        }
    }
}

// ---------------------------------------------------------------------------
// Fused node projections: out_w[M,128] = h @ W_w + b_w for w = blockIdx.y
// ---------------------------------------------------------------------------
__global__ __launch_bounds__(THREADS, 2)
void gemm_node(const float* __restrict__ A,
               const float* __restrict__ W0, const float* __restrict__ W1,
               const float* __restrict__ W2, const float* __restrict__ B0,
               const float* __restrict__ B1, const float* __restrict__ B2,
               float* __restrict__ O0, float* __restrict__ O1,
               float* __restrict__ O2, int M) {
    extern __shared__ uint2 smem[];
    uint2* Wp = smem;
    uint2* Ap = smem + SMEM_W_U2;
    int which = blockIdx.y;
    const float* W = (which == 0) ? W0 : (which == 1) ? W1 : W2;
    const float* bias = (which == 0) ? B0 : (which == 1) ? B1 : B2;
    float* out = (which == 0) ? O0 : (which == 1) ? O1 : O2;

    int tid = threadIdx.x, lane = tid & 31, warp = tid >> 5;
    int wm = (warp & 3) * 16, wn = (warp >> 2) * 32;
    int g = lane >> 2, t = lane & 3;

    stage_W(Wp, W);
    float2 bias2[4];
#pragma unroll
    for (int nf = 0; nf < 4; ++nf)
        bias2[nf] = *(const float2*)&bias[wn + nf * 8 + t * 2];

    int nTiles = (M + TILE_M - 1) / TILE_M;
    int tile = blockIdx.x;
    float4 cur[4];
    if (tile < nTiles) prefetch_A<false>(cur, A, tile * TILE_M, M, tid);
    __syncthreads();

#pragma unroll 1
    for (; tile < nTiles; tile += gridDim.x) {
        store_A(Ap, cur, tid);
        __syncthreads();
        int nxt = tile + gridDim.x;
        if (nxt < nTiles) prefetch_A<false>(cur, A, nxt * TILE_M, M, tid);
        float c[4][4];
#pragma unroll
        for (int j = 0; j < 4; ++j)
#pragma unroll
            for (int k = 0; k < 4; ++k) c[j][k] = 0.f;
        mma_tile(Ap, Wp, wm, wn, lane, c);
        __syncthreads();   // A consumed before next store_A
        int r0 = tile * TILE_M + wm + g;
#pragma unroll
        for (int nf = 0; nf < 4; ++nf) {
            int col = wn + nf * 8 + t * 2;
            if (r0 < M)
                *(float2*)&out[(size_t)r0 * DIM + col] =
                    make_float2(c[nf][0] + bias2[nf].x,
                                c[nf][1] + bias2[nf].y);
            if (r0 + 8 < M)
                *(float2*)&out[(size_t)(r0 + 8) * DIM + col] =
                    make_float2(c[nf][2] + bias2[nf].x,
                                c[nf][3] + bias2[nf].y);
        }
    }
}

// ---------------------------------------------------------------------------
// Fused edge kernel: proj = e @ We + be, then score/e_out/s/scatter
// ---------------------------------------------------------------------------
__global__ __launch_bounds__(THREADS, 2)
void gemm_edge(const float* __restrict__ Ein, const float* __restrict__ W,
               const float* __restrict__ bias, const int* __restrict__ src,
               const int* __restrict__ dst, float* __restrict__ hacc,
               float* __restrict__ eout) {
    extern __shared__ uint2 smem[];
    uint2* Wp = smem;
    uint2* Ap = smem + SMEM_W_U2;
    float* Cs = (float*)(smem + SMEM_W_U2 + SMEM_A_U2);   // dedicated region
    int tid = threadIdx.x, lane = tid & 31, warp = tid >> 5;
    int wm = (warp & 3) * 16, wn = (warp >> 2) * 32;
    int g = lane >> 2, t = lane & 3;

    stage_W(Wp, W);
    float4 be4 = *(const float4*)&bias[lane * 4];

    const int nTiles = N_EDGES / TILE_M;  // 12500 exact
    int tile = blockIdx.x;
    float4 cur[4];
    if (tile < nTiles) prefetch_A<true>(cur, Ein, tile * TILE_M, N_EDGES, tid);
    __syncthreads();

#pragma unroll 1
    for (; tile < nTiles; tile += gridDim.x) {
        store_A(Ap, cur, tid);
        __syncthreads();                       // A published (also: prev Cs reads done)
        float c[4][4];
#pragma unroll
        for (int j = 0; j < 4; ++j)
#pragma unroll
            for (int k = 0; k < 4; ++k) c[j][k] = 0.f;
        mma_tile(Ap, Wp, wm, wn, lane, c);
        // prefetch next tile: overlaps Cs-write + gather/scatter epilogue
        int nxt = tile + gridDim.x;
        if (nxt < nTiles) prefetch_A<true>(cur, Ein, nxt * TILE_M, N_EDGES, tid);
        // write own fragment rows to Cs (no sync needed before: own region)
        {
            int rr = wm + g;
#pragma unroll
            for (int nf = 0; nf < 4; ++nf) {
                int col = wn + nf * 8 + t * 2;
                *(float2*)&Cs[rr * CS_STRIDE + col] =
                    make_float2(c[nf][0], c[nf][1]);
                *(float2*)&Cs[(rr + 8) * CS_STRIDE + col] =
                    make_float2(c[nf][2], c[nf][3]);
            }
        }
        __syncthreads();                       // Cs published; all mma done

        // epilogue: each warp owns 4 edges; 2 at a time, loads batched
        int rbase = warp * 4;
        int ebase = tile * TILE_M + rbase;
        int sn[4], dn[4];
#pragma unroll
        for (int i = 0; i < 4; ++i) {
            sn[i] = __ldg(&src[ebase + i]);
            dn[i] = __ldg(&dst[ebase + i]);
        }
#pragma unroll
        for (int i = 0; i < 4; i += 2) {
            float4 q0 = *(const float4*)&g_Q[(size_t)dn[i] * DIM + lane * 4];
            float4 k0 = *(const float4*)&g_K[(size_t)sn[i] * DIM + lane * 4];
            float4 v0 = *(const float4*)&g_V[(size_t)sn[i] * DIM + lane * 4];
            float4 q1 = *(const float4*)&g_Q[(size_t)dn[i + 1] * DIM + lane * 4];
            float4 k1 = *(const float4*)&g_K[(size_t)sn[i + 1] * DIM + lane * 4];
            float4 v1 = *(const float4*)&g_V[(size_t)sn[i + 1] * DIM + lane * 4];
            float4 p0 = *(float4*)&Cs[(rbase + i) * CS_STRIDE + lane * 4];
            float4 p1 = *(float4*)&Cs[(rbase + i + 1) * CS_STRIDE + lane * 4];
            p0.x += be4.x; p0.y += be4.y; p0.z += be4.z; p0.w += be4.w;
            p1.x += be4.x; p1.y += be4.y; p1.z += be4.z; p1.w += be4.w;

            float4 s0, s1;
            s0.x = q0.x * k0.x * 0.25f * p0.x;
            s0.y = q0.y * k0.y * 0.25f * p0.y;
            s0.z = q0.z * k0.z * 0.25f * p0.z;
            s0.w = q0.w * k0.w * 0.25f * p0.w;
            s1.x = q1.x * k1.x * 0.25f * p1.x;
            s1.y = q1.y * k1.y * 0.25f * p1.y;
            s1.z = q1.z * k1.z * 0.25f * p1.z;
            s1.w = q1.w * k1.w * 0.25f * p1.w;
            __stcs((float4*)&eout[(size_t)(ebase + i) * DIM + lane * 4], s0);
            __stcs((float4*)&eout[(size_t)(ebase + i + 1) * DIM + lane * 4], s1);

            float h0 = s0.x + s0.y + s0.z + s0.w;
            float h1 = s1.x + s1.y + s1.z + s1.w;
            h0 += __shfl_xor_sync(0xffffffffu, h0, 1);
            h0 += __shfl_xor_sync(0xffffffffu, h0, 2);
            h1 += __shfl_xor_sync(0xffffffffu, h1, 1);
            h1 += __shfl_xor_sync(0xffffffffu, h1, 2);
            float e0 = expf(fminf(fmaxf(h0, -5.f), 5.f));
            float e1 = expf(fminf(fmaxf(h1, -5.f), 5.f));

            red_add_v4(&hacc[(size_t)dn[i] * DIM + lane * 4],
                       make_float4(v0.x * e0, v0.y * e0, v0.z * e0, v0.w * e0));
            red_add_v4(&hacc[(size_t)dn[i + 1] * DIM + lane * 4],
                       make_float4(v1.x * e1, v1.y * e1, v1.z * e1, v1.w * e1));
            if ((lane & 3) == 0) {
                red_add_f32(&g_z[dn[i] * HEADS + (lane >> 2)], e0);
                red_add_f32(&g_z[dn[i + 1] * HEADS + (lane >> 2)], e1);
            }
        }
        // no sync here: next iteration's sync (after store_A) orders Cs reuse
    }
}

// ---------------------------------------------------------------------------
// finalize: h_out = wV / (z + 1e-6)
// ---------------------------------------------------------------------------
__global__ void finalize_kernel(float* __restrict__ hacc) {
    int i = blockIdx.x * blockDim.x + threadIdx.x;
    if (i < N_NODES * DIM) {
        int node = i >> 7;
        int head = (i >> 4) & 7;
        hacc[i] = hacc[i] / (g_z[node * HEADS + head] + 1e-6f);
    }
}

// ---------------------------------------------------------------------------
// launch
// ---------------------------------------------------------------------------
extern "C" void kernel_launch(void* const* d_in, const int* in_sizes, int n_in,
                              void* d_out, int out_size) {
    const float* h  = (const float*)d_in[0];
    const float* e  = (const float*)d_in[1];
    const int*   src = (const int*)d_in[2];
    const int*   dst = (const int*)d_in[3];
    const float* Wq = (const float*)d_in[4];
    const float* bq = (const float*)d_in[5];
    const float* Wk = (const float*)d_in[6];
    const float* bk = (const float*)d_in[7];
    const float* Wv = (const float*)d_in[8];
    const float* bv = (const float*)d_in[9];
    const float* We = (const float*)d_in[10];
    const float* be = (const float*)d_in[11];

    float* out  = (float*)d_out;
    float* hacc = out;                               // [N,H,D] accumulator -> h_out
    float* eout = out + (size_t)N_NODES * DIM;       // [E,H,D] e_out

    float *qp, *kp, *vp, *zp;
    cudaGetSymbolAddress((void**)&qp, g_Q);
    cudaGetSymbolAddress((void**)&kp, g_K);
    cudaGetSymbolAddress((void**)&vp, g_V);
    cudaGetSymbolAddress((void**)&zp, g_z);

    cudaFuncSetAttribute(gemm_node, cudaFuncAttributeMaxDynamicSharedMemorySize, NODE_SMEM);
    cudaFuncSetAttribute(gemm_edge, cudaFuncAttributeMaxDynamicSharedMemorySize, EDGE_SMEM);

    cudaMemsetAsync(hacc, 0, (size_t)N_NODES * DIM * sizeof(float));
    cudaMemsetAsync(zp, 0, (size_t)N_NODES * HEADS * sizeof(float));

    dim3 ngrid(GRID, 3);
    gemm_node<<<ngrid, THREADS, NODE_SMEM>>>(h, Wq, Wk, Wv, bq, bk, bv,
                                             qp, kp, vp, N_NODES);
    gemm_edge<<<GRID, THREADS, EDGE_SMEM>>>(e, We, be, src, dst, hacc, eout);
    finalize_kernel<<<(N_NODES * DIM + 255) / 256, 256>>>(hacc);
}